// round 6
// baseline (speedup 1.0000x reference)
#include <cuda_runtime.h>
#include <cstdint>

// MvCnnDownLayer: out[b,h] = relu(conv1dW(in[b,h] + out[b,h-1]) + bias)
// B=16,H=256,W=256,C=32,K=5 (pad 2/2).
// NO CLUSTERS: 16 CTAs (one per batch), 1024 threads each. Each CTA owns the
// full W=256 row; state double-buffered in SMEM, channel-major [c][260]
// (2-halo each side, permanently zero = conv padding).
// Warp w: x-block (w&7)*32, oc-group (w>>3)*8; full 32-channel dot per warp.
// Per-row sync: one __syncthreads. No DSMEM, no cluster barrier, no split-K.

#define Bn 16
#define Hn 256
#define Wn 256
#define Cn 32
#define Kn 5
#define XSTR 260            // 256 interior + 2 halo each side
#define XROWSZ (Cn * XSTR)  // floats per parity buffer
#define NT 1024

__global__ void __launch_bounds__(NT, 1)
mvcnn_down_kernel(const float* __restrict__ in, const float* __restrict__ wg,
                  const float* __restrict__ bias, float* __restrict__ out)
{
    extern __shared__ float smf[];
    float* Xs  = smf;                 // [2][32*260]: idx = parity*XROWSZ + c*260 + (pos+2)
    float* Wsm = smf + 2 * XROWSZ;    // [(k*32+c)*32 + oc]

    const int tid  = threadIdx.x;
    const int lane = tid & 31;
    const int wid  = tid >> 5;        // 0..31
    const int xg   = wid & 7;
    const int ocb  = (wid >> 3) * 8;  // 0,8,16,24
    const int x    = xg * 32 + lane;  // 0..255
    const int b    = blockIdx.x;

    // --- stage weights: Wsm[(k*32+c)*32+oc] = w[(c*5+k)*32+oc] ---
    for (int i2 = tid; i2 < Kn * Cn * Cn; i2 += NT) {
        int oc = i2 & 31;
        int kc = i2 >> 5;
        int c  = kc & 31;
        int k  = kc >> 5;
        Wsm[i2] = wg[(c * Kn + k) * Cn + oc];
    }

    float bv[8];
#pragma unroll
    for (int j = 0; j < 8; ++j) bv[j] = bias[ocb + j];

    // --- zero halo columns: 2 parities x 32 channels x 4 idx (0,1,258,259) ---
    if (tid < 256) {
        int c  = tid >> 3;
        int h  = tid & 7;
        int par = h >> 2;
        int hh  = h & 3;
        int xi  = (hh < 2) ? hh : hh + 256;   // 0,1,258,259
        Xs[par * XROWSZ + c * XSTR + xi] = 0.f;
    }

    const float* inb  = in  + ((size_t)b * Hn * Wn + x) * Cn;
    float*       outb = out + ((size_t)b * Hn * Wn + x) * Cn;
    const size_t rstride = (size_t)Wn * Cn;

    // --- row 0 state: X0 = input row 0 (carry = 0); 4 warps cover all oc-groups ---
    {
        const float4* ip = (const float4*)(inb + ocb);
        float4 v0 = ip[0], v1 = ip[1];
        float* X0 = Xs + 0 * XROWSZ;
        X0[(ocb + 0) * XSTR + 2 + x] = v0.x;
        X0[(ocb + 1) * XSTR + 2 + x] = v0.y;
        X0[(ocb + 2) * XSTR + 2 + x] = v0.z;
        X0[(ocb + 3) * XSTR + 2 + x] = v0.w;
        X0[(ocb + 4) * XSTR + 2 + x] = v1.x;
        X0[(ocb + 5) * XSTR + 2 + x] = v1.y;
        X0[(ocb + 6) * XSTR + 2 + x] = v1.z;
        X0[(ocb + 7) * XSTR + 2 + x] = v1.w;
    }
    __syncthreads();

    for (int i = 0; i < Hn; ++i) {
        const int  p    = i & 1;
        const bool more = (i + 1 < Hn);

        // prefetch next input row (consumed in epilogue, latency hidden by conv)
        float4 pf0 = make_float4(0.f, 0.f, 0.f, 0.f), pf1 = pf0;
        if (more) {
            const float4* np = (const float4*)(inb + (size_t)(i + 1) * rstride + ocb);
            pf0 = np[0];
            pf1 = np[1];
        }

        // --- conv: acc[4 x f32x2] += X[c][x+k] * w[k][c][ocb..ocb+7] ---
        unsigned long long a0 = 0, a1 = 0, a2 = 0, a3 = 0;
        const float* Xp = Xs + p * XROWSZ + x;   // + c*XSTR + k
#pragma unroll
        for (int k = 0; k < Kn; ++k) {
            const ulonglong2* wk = ((const ulonglong2*)Wsm) + (size_t)(k * Cn) * 8 + (ocb >> 2);
            const float* xk = Xp + k;
#pragma unroll
            for (int c = 0; c < Cn; ++c) {
                float xv = xk[c * XSTR];
                unsigned long long xx;
                asm("mov.b64 %0, {%1, %1};" : "=l"(xx) : "r"(__float_as_uint(xv)));
                ulonglong2 wa = wk[c * 8];
                ulonglong2 wb = wk[c * 8 + 1];
                asm("fma.rn.f32x2 %0, %1, %2, %0;" : "+l"(a0) : "l"(xx), "l"(wa.x));
                asm("fma.rn.f32x2 %0, %1, %2, %0;" : "+l"(a1) : "l"(xx), "l"(wa.y));
                asm("fma.rn.f32x2 %0, %1, %2, %0;" : "+l"(a2) : "l"(xx), "l"(wb.x));
                asm("fma.rn.f32x2 %0, %1, %2, %0;" : "+l"(a3) : "l"(xx), "l"(wb.y));
            }
        }

        // --- epilogue: relu(acc + bias), store, build next state ---
        float r[8];
        {
            unsigned lo, hi;
            asm("mov.b64 {%0,%1}, %2;" : "=r"(lo), "=r"(hi) : "l"(a0));
            r[0] = __uint_as_float(lo); r[1] = __uint_as_float(hi);
            asm("mov.b64 {%0,%1}, %2;" : "=r"(lo), "=r"(hi) : "l"(a1));
            r[2] = __uint_as_float(lo); r[3] = __uint_as_float(hi);
            asm("mov.b64 {%0,%1}, %2;" : "=r"(lo), "=r"(hi) : "l"(a2));
            r[4] = __uint_as_float(lo); r[5] = __uint_as_float(hi);
            asm("mov.b64 {%0,%1}, %2;" : "=r"(lo), "=r"(hi) : "l"(a3));
            r[6] = __uint_as_float(lo); r[7] = __uint_as_float(hi);
        }
#pragma unroll
        for (int j = 0; j < 8; ++j) r[j] = fmaxf(r[j] + bv[j], 0.f);

        float4* op = (float4*)(outb + (size_t)i * rstride + ocb);
        op[0] = make_float4(r[0], r[1], r[2], r[3]);
        op[1] = make_float4(r[4], r[5], r[6], r[7]);

        if (more) {
            float* Xn = Xs + (p ^ 1) * XROWSZ;
            Xn[(ocb + 0) * XSTR + 2 + x] = r[0] + pf0.x;
            Xn[(ocb + 1) * XSTR + 2 + x] = r[1] + pf0.y;
            Xn[(ocb + 2) * XSTR + 2 + x] = r[2] + pf0.z;
            Xn[(ocb + 3) * XSTR + 2 + x] = r[3] + pf0.w;
            Xn[(ocb + 4) * XSTR + 2 + x] = r[4] + pf1.x;
            Xn[(ocb + 5) * XSTR + 2 + x] = r[5] + pf1.y;
            Xn[(ocb + 6) * XSTR + 2 + x] = r[6] + pf1.z;
            Xn[(ocb + 7) * XSTR + 2 + x] = r[7] + pf1.w;
        }

        // one CTA-local barrier per row:
        //  - this row's reads of Xs[p] complete before row i+1 overwrites Xs[p]
        //  - this row's writes of Xs[p^1] visible to row i+1's conv
        __syncthreads();
    }
}

extern "C" void kernel_launch(void* const* d_in, const int* in_sizes, int n_in,
                              void* d_out, int out_size)
{
    const float* in   = (const float*)d_in[0];
    const float* w    = (const float*)d_in[1];
    const float* bias = (const float*)d_in[2];
    float* out        = (float*)d_out;
    (void)in_sizes; (void)n_in; (void)out_size;

    const int smem_bytes = (2 * XROWSZ + Kn * Cn * Cn) * sizeof(float); // ~87 KB
    cudaFuncSetAttribute(mvcnn_down_kernel,
                         cudaFuncAttributeMaxDynamicSharedMemorySize, smem_bytes);
    mvcnn_down_kernel<<<dim3(Bn), dim3(NT), smem_bytes>>>(in, w, bias, out);
}

// round 8
// speedup vs baseline: 4.3709x; 4.3709x over previous
#include <cuda_runtime.h>
#include <cuda_bf16.h>
#include <cstdint>

// MvCnnDownLayer via mma.sync (bf16 2-split, fp32 accum):
//   out[b,h] = relu(conv1dW(in[b,h] + out[b,h-1]) + bias)
// B=16,H=256,W=256,C=32,K=5. 16 CTAs (one per batch), 512 thr = 16 warps.
// Per row: D[256,32] = A[256,160] @ W[160,32], K-index = shift*32 + c.
// A = X row in SMEM (bf16 hi/lo planes, rows = x+2 with 2-row zero halo,
// 80B row stride -> conflict-free ldmatrix). Shift handled by per-lane
// ldmatrix row addresses. Warp w = m-tile w (16 x-positions), all 32 oc.
// 3 products per k-tile: Xh*Wh + Xh*Wl + Xl*Wh. One __syncthreads per row.

#define Bn 16
#define Hn 256
#define Wn 256
#define Cn 32
#define NT 512

#define ROWB 80u              // bytes per A/W SMEM row (32 bf16 + 8 pad)
#define APAR 20800u           // 260 rows * 80B per parity buffer
#define OFF_AH 0u
#define OFF_AL (2u * APAR)                 // 41600
#define OFF_WH (4u * APAR)                 // 83200
#define OFF_WL (OFF_WH + 160u * ROWB)      // 96000
#define SMEM_BYTES (96000 + 12800)         // 108800

__device__ __forceinline__ void ldm4(uint32_t a, uint32_t r[4]) {
    asm volatile("ldmatrix.sync.aligned.m8n8.x4.shared.b16 {%0,%1,%2,%3}, [%4];"
                 : "=r"(r[0]), "=r"(r[1]), "=r"(r[2]), "=r"(r[3]) : "r"(a));
}
__device__ __forceinline__ void ldm4t(uint32_t a, uint32_t r[4]) {
    asm volatile("ldmatrix.sync.aligned.m8n8.x4.trans.shared.b16 {%0,%1,%2,%3}, [%4];"
                 : "=r"(r[0]), "=r"(r[1]), "=r"(r[2]), "=r"(r[3]) : "r"(a));
}
__device__ __forceinline__ void mma16816(float d[4], const uint32_t a[4],
                                         uint32_t b0, uint32_t b1) {
    asm volatile("mma.sync.aligned.m16n8k16.row.col.f32.bf16.bf16.f32 "
                 "{%0,%1,%2,%3}, {%4,%5,%6,%7}, {%8,%9}, {%0,%1,%2,%3};"
                 : "+f"(d[0]), "+f"(d[1]), "+f"(d[2]), "+f"(d[3])
                 : "r"(a[0]), "r"(a[1]), "r"(a[2]), "r"(a[3]), "r"(b0), "r"(b1));
}
// pack two floats to bf16x2: low 16 bits = lo, high = hi
__device__ __forceinline__ uint32_t pack2(float lo, float hi) {
    uint32_t r;
    asm("cvt.rn.satfinite.bf16x2.f32 %0, %1, %2;" : "=r"(r) : "f"(hi), "f"(lo));
    return r;
}
__device__ __forceinline__ float bf16rt(float x) {   // bf16 round-trip (hi part)
    return __bfloat162float(__float2bfloat16(x));
}

__global__ void __launch_bounds__(NT, 1)
mvcnn_mma_kernel(const float* __restrict__ in, const float* __restrict__ wg,
                 const float* __restrict__ bias, float* __restrict__ out)
{
    extern __shared__ char smb[];
    const uint32_t smem = (uint32_t)__cvta_generic_to_shared(smb);

    const int tid  = threadIdx.x;
    const int lane = tid & 31;
    const int wid  = tid >> 5;            // m-tile 0..15
    const int b    = blockIdx.x;
    const int mt16 = wid * 16;

    const int q   = lane & 3;             // col-pair within n8
    const int xr  = lane >> 2;            // 0..7
    const int ocq = q * 2;
    const int x0  = mt16 + xr;            // this thread's x rows: x0, x0+8

    // --- stage weights: Wh/Wl bf16, row = K-index (k*32+c), col = oc ---
    for (int idx = tid; idx < 5 * Cn * Cn; idx += NT) {
        int oc = idx & 31, ck = idx >> 5, k = ck % 5, c = ck / 5;
        float w  = wg[idx];                         // wg[(c*5+k)*32+oc]
        float hf = bf16rt(w);
        uint32_t off = (uint32_t)(k * 32 + c) * ROWB + (uint32_t)oc * 2u;
        *(__nv_bfloat16*)(smb + OFF_WH + off) = __float2bfloat16(hf);
        *(__nv_bfloat16*)(smb + OFF_WL + off) = __float2bfloat16(w - hf);
    }

    // --- zero halo rows 0,1,258,259 (both parities, both planes, full 80B) ---
    if (tid < 320) {
        int plane = tid / 80;             // 0,1: AH p0/p1; 2,3: AL p0/p1
        int rem   = tid % 80;
        int r4 = rem / 20, word = rem % 20;
        uint32_t row  = (r4 < 2) ? (uint32_t)r4 : (uint32_t)(256 + r4);
        uint32_t base = (plane < 2 ? OFF_AH : OFF_AL) + (uint32_t)(plane & 1) * APAR;
        *(uint32_t*)(smb + base + row * ROWB + (uint32_t)word * 4u) = 0u;
    }

    // --- bias for this thread's 8 channels ---
    float bv0[4], bv1[4];
#pragma unroll
    for (int j = 0; j < 4; ++j) {
        float2 t = *(const float2*)(bias + ocq + 8 * j);
        bv0[j] = t.x; bv1[j] = t.y;
    }

    // per-lane ldmatrix base: row (lane&15), col-half (lane>>4) (16B)
    const uint32_t frag_base = (uint32_t)(lane & 15) * ROWB + (uint32_t)(lane >> 4) * 16u;

    const size_t bHW = (size_t)b * Hn * Wn;

    // --- row 0 state = in[0] into parity 0 (hi/lo split) ---
#pragma unroll
    for (int s = 0; s < 2; ++s) {
        int x = x0 + s * 8;
        const float* ip = in + (bHW + x) * Cn + ocq;
#pragma unroll
        for (int j = 0; j < 4; ++j) {
            float2 v = *(const float2*)(ip + 8 * j);
            float h0 = bf16rt(v.x), h1 = bf16rt(v.y);
            uint32_t off = (uint32_t)(x + 2) * ROWB + (uint32_t)(ocq + 8 * j) * 2u;
            *(uint32_t*)(smb + OFF_AH + off) = pack2(h0, h1);
            *(uint32_t*)(smb + OFF_AL + off) = pack2(v.x - h0, v.y - h1);
        }
    }
    __syncthreads();

    for (int i = 0; i < Hn; ++i) {
        const int  p    = i & 1;
        const bool more = (i + 1 < Hn);

        // prefetch next input row (hidden behind the mma chain)
        float2 pf[2][4];
        if (more) {
#pragma unroll
            for (int s = 0; s < 2; ++s) {
                const float* ip = in + (bHW + (size_t)(i + 1) * Wn + (x0 + s * 8)) * Cn + ocq;
#pragma unroll
                for (int j = 0; j < 4; ++j) pf[s][j] = *(const float2*)(ip + 8 * j);
            }
        }

        float d[4][4];
#pragma unroll
        for (int j = 0; j < 4; ++j)
#pragma unroll
            for (int e = 0; e < 4; ++e) d[j][e] = 0.f;

        const uint32_t aH = smem + OFF_AH + (uint32_t)p * APAR + frag_base;
        const uint32_t aL = smem + OFF_AL + (uint32_t)p * APAR + frag_base;
        const uint32_t wH = smem + OFF_WH + frag_base;
        const uint32_t wL = smem + OFF_WL + frag_base;

#pragma unroll
        for (int kt = 0; kt < 10; ++kt) {
            const int k = kt >> 1, ch = kt & 1;
            const uint32_t aoff = (uint32_t)(mt16 + k) * ROWB + (uint32_t)ch * 32u;
            const uint32_t boff = (uint32_t)kt * (16u * ROWB);
            uint32_t ah[4], al[4], bh0[4], bh1[4], bl0[4], bl1[4];
            ldm4(aH + aoff, ah);
            ldm4(aL + aoff, al);
            ldm4t(wH + boff,       bh0);   // oc 0..15
            ldm4t(wH + boff + 32u, bh1);   // oc 16..31
            ldm4t(wL + boff,       bl0);
            ldm4t(wL + boff + 32u, bl1);
            mma16816(d[0], ah, bh0[0], bh0[1]);
            mma16816(d[1], ah, bh0[2], bh0[3]);
            mma16816(d[2], ah, bh1[0], bh1[1]);
            mma16816(d[3], ah, bh1[2], bh1[3]);
            mma16816(d[0], ah, bl0[0], bl0[1]);
            mma16816(d[1], ah, bl0[2], bl0[3]);
            mma16816(d[2], ah, bl1[0], bl1[1]);
            mma16816(d[3], ah, bl1[2], bl1[3]);
            mma16816(d[0], al, bh0[0], bh0[1]);
            mma16816(d[1], al, bh0[2], bh0[3]);
            mma16816(d[2], al, bh1[0], bh1[1]);
            mma16816(d[3], al, bh1[2], bh1[3]);
        }

        // --- epilogue: relu(d+bias), store out, build next state ---
        float* op = out + (bHW + (size_t)i * Wn) * Cn;
        const uint32_t wrAH = OFF_AH + (uint32_t)(p ^ 1) * APAR;
        const uint32_t wrAL = OFF_AL + (uint32_t)(p ^ 1) * APAR;
#pragma unroll
        for (int s = 0; s < 2; ++s) {
            const int x = x0 + s * 8;
#pragma unroll
            for (int j = 0; j < 4; ++j) {
                const int oc = ocq + 8 * j;
                float v0 = fmaxf(d[j][2 * s + 0] + bv0[j], 0.f);
                float v1 = fmaxf(d[j][2 * s + 1] + bv1[j], 0.f);
                *(float2*)(op + (size_t)x * Cn + oc) = make_float2(v0, v1);
                if (more) {
                    float xn0 = v0 + pf[s][j].x;
                    float xn1 = v1 + pf[s][j].y;
                    float h0 = bf16rt(xn0), h1 = bf16rt(xn1);
                    uint32_t off = (uint32_t)(x + 2) * ROWB + (uint32_t)oc * 2u;
                    *(uint32_t*)(smb + wrAH + off) = pack2(h0, h1);
                    *(uint32_t*)(smb + wrAL + off) = pack2(xn0 - h0, xn1 - h1);
                }
            }
        }
        __syncthreads();
    }
}

extern "C" void kernel_launch(void* const* d_in, const int* in_sizes, int n_in,
                              void* d_out, int out_size)
{
    const float* in   = (const float*)d_in[0];
    const float* w    = (const float*)d_in[1];
    const float* bias = (const float*)d_in[2];
    float* out        = (float*)d_out;
    (void)in_sizes; (void)n_in; (void)out_size;

    cudaFuncSetAttribute(mvcnn_mma_kernel,
                         cudaFuncAttributeMaxDynamicSharedMemorySize, SMEM_BYTES);
    mvcnn_mma_kernel<<<dim3(Bn), dim3(NT), SMEM_BYTES>>>(in, w, bias, out);
}

// round 9
// speedup vs baseline: 5.4573x; 1.2486x over previous
#include <cuda_runtime.h>
#include <cuda_bf16.h>
#include <cstdint>

// MvCnnDownLayer via mma.sync bf16 2-split (3 products, fp32 accum), W-split
// across 2-CTA clusters:
//   out[b,h] = relu(conv1dW(in[b,h] + out[b,h-1]) + bias)
// B=16,H=256,W=256,C=32,K=5. Grid 32 = 16 clusters x 2 CTAs, 512 thr.
// CTA owns 128 x (8 m16-tiles); A = X row bf16 hi/lo planes, 132 rows (2 halo
// each side), 80B stride. Warp (tile, khalf): khalf 0/1 does k-tiles 0-4 / 5-9
// (60 HMMA each); partials combined via SMEM (80B-stride, conflict-free).
// Halo: 2 edge columns -> neighbor via st.shared::cluster; one barrier.cluster/row.

#define Bn 16
#define Hn 256
#define Wn 256
#define Cn 32
#define NT 512

#define ROWB 80u                    // bytes per A/W SMEM row (32 bf16 + pad)
#define APAR (132u * ROWB)          // 10560 per parity per plane
#define OFF_AH 0u
#define OFF_AL 21120u
#define OFF_WH 42240u               // 160 rows x 80B
#define OFF_WL 55040u
#define OFF_RED 67840u              // 8 tiles x 32 lanes x 80B
#define SMEM_BYTES 88320u

__device__ __forceinline__ void ldm4(uint32_t a, uint32_t r[4]) {
    asm volatile("ldmatrix.sync.aligned.m8n8.x4.shared.b16 {%0,%1,%2,%3}, [%4];"
                 : "=r"(r[0]), "=r"(r[1]), "=r"(r[2]), "=r"(r[3]) : "r"(a));
}
__device__ __forceinline__ void ldm4t(uint32_t a, uint32_t r[4]) {
    asm volatile("ldmatrix.sync.aligned.m8n8.x4.trans.shared.b16 {%0,%1,%2,%3}, [%4];"
                 : "=r"(r[0]), "=r"(r[1]), "=r"(r[2]), "=r"(r[3]) : "r"(a));
}
__device__ __forceinline__ void mma16816(float d[4], const uint32_t a[4],
                                         uint32_t b0, uint32_t b1) {
    asm volatile("mma.sync.aligned.m16n8k16.row.col.f32.bf16.bf16.f32 "
                 "{%0,%1,%2,%3}, {%4,%5,%6,%7}, {%8,%9}, {%0,%1,%2,%3};"
                 : "+f"(d[0]), "+f"(d[1]), "+f"(d[2]), "+f"(d[3])
                 : "r"(a[0]), "r"(a[1]), "r"(a[2]), "r"(a[3]), "r"(b0), "r"(b1));
}
__device__ __forceinline__ uint32_t pack2(float lo, float hi) {
    uint32_t r;
    asm("cvt.rn.satfinite.bf16x2.f32 %0, %1, %2;" : "=r"(r) : "f"(hi), "f"(lo));
    return r;
}
__device__ __forceinline__ float bf16rt(float x) {
    return __bfloat162float(__float2bfloat16(x));
}

__global__ void __cluster_dims__(2, 1, 1) __launch_bounds__(NT, 1)
mvcnn_mma2_kernel(const float* __restrict__ in, const float* __restrict__ wg,
                  const float* __restrict__ bias, float* __restrict__ out)
{
    extern __shared__ char smb[];
    const uint32_t smem = (uint32_t)__cvta_generic_to_shared(smb);

    const int tid   = threadIdx.x;
    const int lane  = tid & 31;
    const int wid   = tid >> 5;          // 0..15
    const int tile  = wid & 7;           // m16-tile within segment
    const int khalf = wid >> 3;          // 0: kt 0-4, 1: kt 5-9
    const int b     = blockIdx.x >> 1;
    const int rank  = blockIdx.x & 1;
    const int seg   = rank * 128;

    const int q   = lane & 3;
    const int xr  = lane >> 2;
    const int ocq = q * 2;
    const int xl0 = tile * 16 + xr;      // local x; this thread: xl0, xl0+8

    // --- stage weights: row = k*32+c, col = oc; bf16 hi/lo planes ---
    for (int idx = tid; idx < 5 * Cn * Cn; idx += NT) {
        int oc = idx & 31, ck = idx >> 5, k = ck % 5, c = ck / 5;
        float w  = wg[idx];
        float hf = bf16rt(w);
        uint32_t off = (uint32_t)(k * 32 + c) * ROWB + (uint32_t)oc * 2u;
        *(__nv_bfloat16*)(smb + OFF_WH + off) = __float2bfloat16(hf);
        *(__nv_bfloat16*)(smb + OFF_WL + off) = __float2bfloat16(w - hf);
    }

    // --- zero edge-of-image halo rows (both parities, both planes) ---
    // rank0: ax 0,1 (x=-2,-1); rank1: ax 130,131 (x=256,257)
    if (tid < 160) {
        int word = tid % 20;
        int r    = tid / 20;             // row(2) x parity(2) x plane(2)
        int rr   = r & 1;
        int par  = (r >> 1) & 1;
        int pl   = r >> 2;
        uint32_t ax   = (rank == 0) ? (uint32_t)rr : (uint32_t)(130 + rr);
        uint32_t base = (pl ? OFF_AL : OFF_AH) + (uint32_t)par * APAR;
        *(uint32_t*)(smb + base + ax * ROWB + (uint32_t)word * 4u) = 0u;
    }

    const size_t bHW = (size_t)b * Hn * Wn;

    // --- row-0 interior halo from global (parity 0) ---
    // rank0: ax 130,131 <- x 128,129 ; rank1: ax 0,1 <- x 126,127
    if (tid < 32) {
        int r  = tid >> 4;               // 0..1
        int cp = tid & 15;               // channel pair
        int gx = (rank == 0) ? (128 + r) : (126 + r);
        uint32_t ax = (rank == 0) ? (uint32_t)(130 + r) : (uint32_t)r;
        float2 v = *(const float2*)(in + (bHW + gx) * Cn + cp * 2);
        float h0 = bf16rt(v.x), h1 = bf16rt(v.y);
        uint32_t off = ax * ROWB + (uint32_t)cp * 4u;
        *(uint32_t*)(smb + OFF_AH + off) = pack2(h0, h1);
        *(uint32_t*)(smb + OFF_AL + off) = pack2(v.x - h0, v.y - h1);
    }

    // --- bias (epilogue warps) ---
    float bv0[4], bv1[4];
    if (khalf == 0) {
#pragma unroll
        for (int j = 0; j < 4; ++j) {
            float2 t = *(const float2*)(bias + ocq + 8 * j);
            bv0[j] = t.x; bv1[j] = t.y;
        }
    }

    const uint32_t frag_base = (uint32_t)(lane & 15) * ROWB + (uint32_t)(lane >> 4) * 16u;

    // --- row-0 interior state = in[0] (epilogue warps) ---
    if (khalf == 0) {
#pragma unroll
        for (int s = 0; s < 2; ++s) {
            int lx = xl0 + s * 8;
            const float* ip = in + (bHW + (seg + lx)) * Cn + ocq;
#pragma unroll
            for (int j = 0; j < 4; ++j) {
                float2 v = *(const float2*)(ip + 8 * j);
                float h0 = bf16rt(v.x), h1 = bf16rt(v.y);
                uint32_t off = (uint32_t)(lx + 2) * ROWB + (uint32_t)(ocq + 8 * j) * 2u;
                *(uint32_t*)(smb + OFF_AH + off) = pack2(h0, h1);
                *(uint32_t*)(smb + OFF_AL + off) = pack2(v.x - h0, v.y - h1);
            }
        }
    }
    __syncthreads();

    // --- remote SMEM base of partner CTA ---
    uint32_t rbase;
    asm("mapa.shared::cluster.u32 %0, %1, %2;" : "=r"(rbase) : "r"(smem), "r"(rank ^ 1));

    for (int i = 0; i < Hn; ++i) {
        const int  p    = i & 1;
        const bool more = (i + 1 < Hn);

        // prefetch next input row (epilogue warps; hidden behind MMA chain)
        float2 pf[2][4];
        if (more && khalf == 0) {
#pragma unroll
            for (int s = 0; s < 2; ++s) {
                const float* ip = in + (bHW + (size_t)(i + 1) * Wn + (seg + xl0 + s * 8)) * Cn + ocq;
#pragma unroll
                for (int j = 0; j < 4; ++j) pf[s][j] = *(const float2*)(ip + 8 * j);
            }
        }

        float d[4][4];
#pragma unroll
        for (int j = 0; j < 4; ++j)
#pragma unroll
            for (int e = 0; e < 4; ++e) d[j][e] = 0.f;

        const uint32_t aH = smem + OFF_AH + (uint32_t)p * APAR + frag_base;
        const uint32_t aL = smem + OFF_AL + (uint32_t)p * APAR + frag_base;
        const uint32_t wH = smem + OFF_WH + frag_base;
        const uint32_t wL = smem + OFF_WL + frag_base;

#pragma unroll
        for (int kti = 0; kti < 5; ++kti) {
            const int kt = khalf * 5 + kti;
            const int k = kt >> 1, ch = kt & 1;
            const uint32_t aoff = (uint32_t)(tile * 16 + k) * ROWB + (uint32_t)ch * 32u;
            const uint32_t boff = (uint32_t)kt * (16u * ROWB);
            uint32_t ah[4], al[4], bh0[4], bh1[4], bl0[4], bl1[4];
            ldm4(aH + aoff, ah);
            ldm4(aL + aoff, al);
            ldm4t(wH + boff,       bh0);
            ldm4t(wH + boff + 32u, bh1);
            ldm4t(wL + boff,       bl0);
            ldm4t(wL + boff + 32u, bl1);
            mma16816(d[0], ah, bh0[0], bh0[1]);
            mma16816(d[1], ah, bh0[2], bh0[3]);
            mma16816(d[2], ah, bh1[0], bh1[1]);
            mma16816(d[3], ah, bh1[2], bh1[3]);
            mma16816(d[0], ah, bl0[0], bl0[1]);
            mma16816(d[1], ah, bl0[2], bl0[3]);
            mma16816(d[2], ah, bl1[0], bl1[1]);
            mma16816(d[3], ah, bl1[2], bl1[3]);
            mma16816(d[0], al, bh0[0], bh0[1]);
            mma16816(d[1], al, bh0[2], bh0[3]);
            mma16816(d[2], al, bh1[0], bh1[1]);
            mma16816(d[3], al, bh1[2], bh1[3]);
        }

        // --- khalf1 publishes partials (80B lane stride: conflict-free) ---
        if (khalf == 1) {
            char* rp = smb + OFF_RED + (uint32_t)tile * (32u * ROWB) + (uint32_t)lane * ROWB;
#pragma unroll
            for (int j = 0; j < 4; ++j)
                *(float4*)(rp + j * 16) = make_float4(d[j][0], d[j][1], d[j][2], d[j][3]);
        }
        __syncthreads();

        if (khalf == 0) {
            const char* rp = smb + OFF_RED + (uint32_t)tile * (32u * ROWB) + (uint32_t)lane * ROWB;
#pragma unroll
            for (int j = 0; j < 4; ++j) {
                float4 t = *(const float4*)(rp + j * 16);
                d[j][0] += t.x; d[j][1] += t.y; d[j][2] += t.z; d[j][3] += t.w;
            }

            // --- epilogue: relu(d+bias), STG, next state (+remote edge halo) ---
            float* op = out + (bHW + (size_t)i * Wn) * Cn;
            const uint32_t wAH = OFF_AH + (uint32_t)(p ^ 1) * APAR;
            const uint32_t wAL = OFF_AL + (uint32_t)(p ^ 1) * APAR;
#pragma unroll
            for (int s = 0; s < 2; ++s) {
                const int lx = xl0 + s * 8;
                const bool edge = (rank == 0) ? (lx >= 126) : (lx < 2);
                const uint32_t rax = (rank == 0) ? (uint32_t)(lx - 126) : (uint32_t)(130 + lx);
#pragma unroll
                for (int j = 0; j < 4; ++j) {
                    const int oc = ocq + 8 * j;
                    float v0 = fmaxf(d[j][2 * s + 0] + bv0[j], 0.f);
                    float v1 = fmaxf(d[j][2 * s + 1] + bv1[j], 0.f);
                    *(float2*)(op + (size_t)(seg + lx) * Cn + oc) = make_float2(v0, v1);
                    if (more) {
                        float xn0 = v0 + pf[s][j].x;
                        float xn1 = v1 + pf[s][j].y;
                        float h0 = bf16rt(xn0), h1 = bf16rt(xn1);
                        uint32_t ph = pack2(h0, h1);
                        uint32_t pl = pack2(xn0 - h0, xn1 - h1);
                        uint32_t off = (uint32_t)(lx + 2) * ROWB + (uint32_t)oc * 2u;
                        *(uint32_t*)(smb + wAH + off) = ph;
                        *(uint32_t*)(smb + wAL + off) = pl;
                        if (edge) {
                            uint32_t roff = rax * ROWB + (uint32_t)oc * 2u;
                            asm volatile("st.shared::cluster.b32 [%0], %1;"
                                         :: "r"(rbase + wAH + roff), "r"(ph) : "memory");
                            asm volatile("st.shared::cluster.b32 [%0], %1;"
                                         :: "r"(rbase + wAL + roff), "r"(pl) : "memory");
                        }
                    }
                }
            }
        }

        // cluster barrier: releases local + remote state writes, bounds skew
        if (more)
            asm volatile("barrier.cluster.arrive.aligned;\n\tbarrier.cluster.wait.aligned;"
                         ::: "memory");
    }
}

extern "C" void kernel_launch(void* const* d_in, const int* in_sizes, int n_in,
                              void* d_out, int out_size)
{
    const float* in   = (const float*)d_in[0];
    const float* w    = (const float*)d_in[1];
    const float* bias = (const float*)d_in[2];
    float* out        = (float*)d_out;
    (void)in_sizes; (void)n_in; (void)out_size;

    cudaFuncSetAttribute(mvcnn_mma2_kernel,
                         cudaFuncAttributeMaxDynamicSharedMemorySize, SMEM_BYTES);
    mvcnn_mma2_kernel<<<dim3(Bn * 2), dim3(NT), SMEM_BYTES>>>(in, w, bias, out);
}